// round 15
// baseline (speedup 1.0000x reference)
#include <cuda_runtime.h>
#include <cuda_fp16.h>
#include <cuda_bf16.h>
#include <cstdint>
#include <cstddef>

// out = W[4096x128] @ Aug[128x16384] via mma.sync fp16.
// K1: factor table + Kvec chain (block 0) OVERLAPPED with u transpose (128).
// K2: W P-half products (blocks 0-63) CONCURRENT with scan (blocks 64-191).
// K3: persistent GEMM.

#define NCHUNK 16
#define BHTOT  1024
#define NCOLS  (NCHUNK * BHTOT)   // 16384

// ---------------- scratch (static device memory) --------------------------
__device__ float g_Kvec[64 * 64];           // K_d = A^d B
__device__ float g_Pow[7 * 4096];           // A^(2^i), i=0..6 (fp32); [6]=A^64
__device__ __align__(16) float g_UT[(size_t)BHTOT * 1024];  // u transposed
__device__ __align__(16) __half g_WH[64 * 8192];            // W fp16, per k 64x128
__device__ __align__(16) __half g_AugH[(size_t)NCOLS * 128];  // fp16(Aug)

// perm16: physical row within a 16-row W group for true n (epilogue float4)
__device__ __forceinline__ int perm16(int m) {
    return ((m >> 1) & 1) * 8 + (m >> 2) * 2 + (m & 1);
}

// ---------------- helpers ----------------
__device__ __forceinline__ uint32_t smem_u32(const void* p) {
    uint32_t a;
    asm("{ .reg .u64 t; cvta.to.shared.u64 t, %1; cvt.u32.u64 %0, t; }"
        : "=r"(a) : "l"(p));
    return a;
}
__device__ __forceinline__ void ldsm4(uint32_t* r, uint32_t addr) {
    asm volatile("ldmatrix.sync.aligned.m8n8.x4.shared.b16 {%0,%1,%2,%3}, [%4];"
                 : "=r"(r[0]), "=r"(r[1]), "=r"(r[2]), "=r"(r[3]) : "r"(addr));
}
__device__ __forceinline__ void mma16816(float* d, const uint32_t* a,
                                         const uint32_t* b) {
    asm volatile(
        "mma.sync.aligned.m16n8k16.row.col.f32.f16.f16.f32 "
        "{%0,%1,%2,%3},{%4,%5,%6,%7},{%8,%9},{%0,%1,%2,%3};"
        : "+f"(d[0]), "+f"(d[1]), "+f"(d[2]), "+f"(d[3])
        : "r"(a[0]), "r"(a[1]), "r"(a[2]), "r"(a[3]), "r"(b[0]), "r"(b[1]));
}
__device__ __forceinline__ void mma16816bf(float* d, const uint32_t* a,
                                           const uint32_t* b) {
    asm volatile(
        "mma.sync.aligned.m16n8k16.row.col.f32.bf16.bf16.f32 "
        "{%0,%1,%2,%3},{%4,%5,%6,%7},{%8,%9},{%0,%1,%2,%3};"
        : "+f"(d[0]), "+f"(d[1]), "+f"(d[2]), "+f"(d[3])
        : "r"(a[0]), "r"(a[1]), "r"(a[2]), "r"(a[3]), "r"(b[0]), "r"(b[1]));
}
__device__ __forceinline__ void cp16(uint32_t dst, const void* src) {
    asm volatile("cp.async.cg.shared.global [%0], [%1], 16;"
                 :: "r"(dst), "l"(src));
}
__device__ __forceinline__ void cp_commit() {
    asm volatile("cp.async.commit_group;" ::: "memory");
}
template <int N>
__device__ __forceinline__ void cp_wait_n() {
    asm volatile("cp.async.wait_group %0;" :: "n"(N) : "memory");
}

// ---------------- tensor-core 64x64 product (bf16x3) ----------------------
// Matrix group = 4 bf16 buffers (64x72): H_row, L_row, H_trans, L_trans.
#define TCP    72
#define BUFE   4608
#define GRPE   (4 * BUFE)
#define PREP1_SMEM 36864            // bf16 group / fp32 scratch / u-stage
#define POW2_SMEM (2 * GRPE * 2)    // 73728 B (two groups)

__device__ __forceinline__ void pow_write(__nv_bfloat16* sm, int gD,
                                          int r, int c, float v) {
    __nv_bfloat16 hi = __float2bfloat16(v);
    __nv_bfloat16 lo = __float2bfloat16(v - __bfloat162float(hi));
    sm[gD + r * TCP + c]                = hi;
    sm[gD + BUFE + r * TCP + c]         = lo;
    sm[gD + 2 * BUFE + c * TCP + r]     = hi;
    sm[gD + 3 * BUFE + c * TCP + r]     = lo;
}

// D(group gD) = gA x gB; 256 threads; aliasing safe (reads before sync)
__device__ __forceinline__ void mm_tc(__nv_bfloat16* sm, uint32_t smb,
                                      int tid, int gA, int gB, int gD) {
    const int lane = tid & 31, wid = tid >> 5;
    const int m0 = (wid >> 1) * 16;
    const int n0 = (wid & 1) * 32;
    const uint32_t aRow = (lane & 7) + ((lane >> 3) & 1) * 8;
    const uint32_t aOff = ((lane >> 4) & 1) * 16;
    const uint32_t bRow = (lane & 7) + ((lane >> 4) & 1) * 8;
    const uint32_t bOff = ((lane >> 3) & 1) * 16;
    const uint32_t aB  = smb + (uint32_t)gA * 2 + (m0 + aRow) * 144 + aOff;
    const uint32_t b0B = smb + (uint32_t)(gB + 2 * BUFE) * 2
                             + (n0 + bRow) * 144 + bOff;
    const uint32_t b1B = b0B + 16 * 144;

    float acc[4][4];
#pragma unroll
    for (int nt = 0; nt < 4; nt++)
#pragma unroll
        for (int r = 0; r < 4; r++) acc[nt][r] = 0.0f;

#pragma unroll
    for (int k = 0; k < 4; k++) {
        uint32_t ah[4], al[4], b0h[4], b0l[4], b1h[4], b1l[4];
        ldsm4(ah,  aB + k * 32);
        ldsm4(al,  aB + BUFE * 2 + k * 32);
        ldsm4(b0h, b0B + k * 32);
        ldsm4(b0l, b0B + BUFE * 2 + k * 32);
        ldsm4(b1h, b1B + k * 32);
        ldsm4(b1l, b1B + BUFE * 2 + k * 32);
        mma16816bf(acc[0], ah, &b0h[0]); mma16816bf(acc[1], ah, &b0h[2]);
        mma16816bf(acc[2], ah, &b1h[0]); mma16816bf(acc[3], ah, &b1h[2]);
        mma16816bf(acc[0], ah, &b0l[0]); mma16816bf(acc[1], ah, &b0l[2]);
        mma16816bf(acc[2], ah, &b1l[0]); mma16816bf(acc[3], ah, &b1l[2]);
        mma16816bf(acc[0], al, &b0h[0]); mma16816bf(acc[1], al, &b0h[2]);
        mma16816bf(acc[2], al, &b1h[0]); mma16816bf(acc[3], al, &b1h[2]);
    }
    __syncthreads();
    const int r0 = m0 + (lane >> 2);
#pragma unroll
    for (int nt = 0; nt < 4; nt++) {
        const int c0 = n0 + nt * 8 + (lane & 3) * 2;
        pow_write(sm, gD, r0,     c0,     acc[nt][0]);
        pow_write(sm, gD, r0,     c0 + 1, acc[nt][1]);
        pow_write(sm, gD, r0 + 8, c0,     acc[nt][2]);
        pow_write(sm, gD, r0 + 8, c0 + 1, acc[nt][3]);
    }
    __syncthreads();
}

// ---------------- K1: block 0 = factor chain + Kvec; 1-128 = u transpose --
__global__ void __launch_bounds__(256, 1) prep1_kernel(
    const float* __restrict__ A, const float* __restrict__ Bv,
    const float* __restrict__ inp) {
    extern __shared__ __nv_bfloat16 smraw[];
    const int tid = threadIdx.x;

    if (blockIdx.x == 0) {
        // ---- factor chain A^(2^i) ----
        __nv_bfloat16* sm = smraw;
        const uint32_t smb = smem_u32(sm);
        for (int i = tid; i < 4096; i += 256) {
            float v = A[i];
            g_Pow[i] = v;
            pow_write(sm, 0, i >> 6, i & 63, v);
        }
        __syncthreads();
#pragma unroll 1
        for (int st = 1; st <= 6; st++) {
            mm_tc(sm, smb, tid, 0, 0, 0);     // pw = pw x pw
            for (int i = tid; i < 4096; i += 256) {
                int n = i >> 6, m = i & 63;
                g_Pow[st * 4096 + i] =
                    __bfloat162float(sm[n * TCP + m]) +
                    __bfloat162float(sm[BUFE + n * TCP + m]);
            }
        }
        __syncthreads();
        // ---- Kvec chain: K_0 = B; K_d = A K_{d-1} (fp32, pitch 65) ----
        float* sf = reinterpret_cast<float*>(smraw);   // A at pitch 65
        float* kb = sf + 4160;                          // 2 x 64 double buffer
        for (int i = tid; i < 4096; i += 256)
            sf[(i >> 6) * 65 + (i & 63)] = A[i];
        if (tid < 64) {
            float v = Bv[tid];
            kb[tid] = v;
            g_Kvec[tid] = v;
        }
        __syncthreads();
#pragma unroll 1
        for (int d = 1; d < 64; d++) {
            const float* src = kb + ((d - 1) & 1) * 64;
            float* dst = kb + (d & 1) * 64;
            if (tid < 64) {
                float a = 0.0f;
#pragma unroll 8
                for (int q = 0; q < 64; q++)
                    a = fmaf(sf[tid * 65 + q], src[q], a);
                dst[tid] = a;
                g_Kvec[d * 64 + tid] = a;
            }
            __syncthreads();
        }
    } else {
        // ---- u transpose: 8 heads x 1024 steps -> g_UT + Aug u-half ----
        float* su = reinterpret_cast<float*>(smraw);     // 8 x 1032
        const int bh0 = (blockIdx.x - 1) * 8;
        const int b   = bh0 >> 8;
        const int h0  = bh0 & 255;
        const float* src = inp + (size_t)b * 1024 * 256 + h0;
        const int hh = tid & 7;
        const int tb = tid >> 3;
#pragma unroll 4
        for (int it = 0; it < 32; it++) {
            int t = it * 32 + tb;
            su[hh * 1032 + t] = src[(size_t)t * 256 + hh];
        }
        __syncthreads();
        for (int idx = tid; idx < 2048; idx += 256) {
            int row = idx >> 8, c4 = idx & 255;
            const float* s = su + row * 1032 + c4 * 4;
            float4 v = make_float4(s[0], s[1], s[2], s[3]);
            *reinterpret_cast<float4*>(g_UT + (size_t)(bh0 + row) * 1024
                                       + c4 * 4) = v;
        }
        for (int idx = tid; idx < 8192; idx += 256) {
            int j = idx >> 9, h2 = (idx >> 6) & 7, s = idx & 63;
            g_AugH[(size_t)(j * 1024 + bh0 + h2) * 128 + 64 + s] =
                __float2half(su[h2 * 1032 + j * 64 + s]);
        }
    }
}

// ---------------- K2: blocks 0-63 W P-half; blocks 64-191 scan ------------
#define VS_OFF_K  8256      // floats: su 8x1032, then sK 4096, sP 64x65, sbuf

__device__ void powers2_body(__nv_bfloat16* sm, int c, int tid) {
    const uint32_t smb = smem_u32(sm);
    const int e = c + 1;          // 1..64

    int bits = e;
    const int first = __ffs(bits) - 1;
    bits &= bits - 1;
    for (int i = tid; i < 4096; i += 256)
        pow_write(sm, 0, i >> 6, i & 63, g_Pow[first * 4096 + i]);
    __syncthreads();

    while (bits) {
        const int b = __ffs(bits) - 1;
        bits &= bits - 1;
        for (int i = tid; i < 4096; i += 256)
            pow_write(sm, GRPE, i >> 6, i & 63, g_Pow[b * 4096 + i]);
        __syncthreads();
        mm_tc(sm, smb, tid, 0, GRPE, 0);   // res = res x fac (powers commute)
    }

    // W P-half (perm16 rows)
    for (int i = tid; i < 4096; i += 256) {
        int n = i >> 6, m = i & 63;
        float v = __bfloat162float(sm[n * TCP + m])
                + __bfloat162float(sm[BUFE + n * TCP + m]);
        int np = (n & 48) | perm16(n & 15);
        g_WH[(size_t)c * 8192 + np * 128 + m] = __float2half(v);
    }
}

__device__ void scan_body(float* vs, int bid, int tid,
                          const float* __restrict__ x0) {
    float* su   = vs;              // 8 x 1032
    float* sK   = vs + 8256;       // 4096
    float* sP   = vs + 12352;      // 64 x 65
    float* sbuf = vs + 16512;      // 8 x 64
    const int bh0 = bid * 8;

    for (int idx = tid; idx < 2048; idx += 256) {
        int row = idx >> 8, c4 = idx & 255;
        float4 v = *reinterpret_cast<const float4*>(
            g_UT + (size_t)(bh0 + row) * 1024 + c4 * 4);
        float* d = su + row * 1032 + c4 * 4;
        d[0] = v.x; d[1] = v.y; d[2] = v.z; d[3] = v.w;
    }
    for (int i = tid; i < 4096; i += 256) {
        sK[i] = g_Kvec[i];
        sP[(i >> 6) * 65 + (i & 63)] = g_Pow[6 * 4096 + i];   // A^64
    }
    __syncthreads();

    // W K-half triangle (perm16 rows): this CTA's 2048-element slice
    {
        int base_i = bid * 2048;
        for (int ii = tid; ii < 2048; ii += 256) {
            int idx = base_i + ii;
            int k = idx >> 12, n = (idx >> 6) & 63, s = idx & 63;
            float val = (s <= k) ? sK[(k - s) * 64 + n] : 0.0f;
            int np = (n & 48) | perm16(n & 15);
            g_WH[(size_t)k * 8192 + np * 128 + 64 + s] = __float2half(val);
        }
    }

    const int w = tid >> 5, lane = tid & 31;
    const int bh = bh0 + w;
    float s0 = x0[(size_t)bh * 64 + lane];
    float s1 = x0[(size_t)bh * 64 + lane + 32];
    g_AugH[(size_t)bh * 128 + lane]      = __float2half(s0);
    g_AugH[(size_t)bh * 128 + lane + 32] = __float2half(s1);
#pragma unroll 1
    for (int j = 1; j < 16; j++) {
        sbuf[w * 64 + lane]      = s0;
        sbuf[w * 64 + lane + 32] = s1;
        __syncwarp();
        float a0 = 0.0f, a1 = 0.0f;
        const float* uj = su + w * 1032 + (j - 1) * 64;
#pragma unroll 8
        for (int s = 0; s < 64; s++) {
            float u = uj[s];
            a0 = fmaf(sK[(63 - s) * 64 + lane], u, a0);
            a1 = fmaf(sK[(63 - s) * 64 + lane + 32], u, a1);
        }
#pragma unroll 8
        for (int q = 0; q < 64; q++) {
            float xq = sbuf[w * 64 + q];
            a0 = fmaf(sP[lane * 65 + q], xq, a0);
            a1 = fmaf(sP[(lane + 32) * 65 + q], xq, a1);
        }
        __syncwarp();
        s0 = a0; s1 = a1;
        g_AugH[(size_t)(j * 1024 + bh) * 128 + lane]      = __float2half(s0);
        g_AugH[(size_t)(j * 1024 + bh) * 128 + lane + 32] = __float2half(s1);
    }
}

__global__ void __launch_bounds__(256, 1) prep2_kernel(
    const float* __restrict__ x0) {
    extern __shared__ __nv_bfloat16 smraw[];
    const int tid = threadIdx.x;
    if (blockIdx.x < 64)
        powers2_body(smraw, blockIdx.x, tid);
    else
        scan_body(reinterpret_cast<float*>(smraw), blockIdx.x - 64, tid, x0);
}

// ---------------- persistent mma.sync GEMM, weighted static schedule ------
#define PITCH    272
#define GEMM_SMEM (384 * 272)    // 104448
#define NGRID    296
#define WTOT     38912ull        // 256 groups x 152

__device__ __forceinline__ void load_w(uint32_t base, int tid, int kg, int nh,
                                       int buf, int steps) {
    const int qmax = 2 * steps;
    const __half* wsrc = g_WH + (size_t)(kg * 4 + nh * 2) * 64 * 128;
    uint32_t dst0 = base + (128 + buf * 128) * PITCH;
    for (int i = tid; i < 2048; i += 512) {
        int row = i >> 4, q = i & 15;
        if (q < qmax)
            cp16(dst0 + row * PITCH + q * 16, wsrc + (size_t)row * 128 + q * 8);
    }
    cp_commit();
}

template <int STEPS>
__device__ __forceinline__ void gemm_iter(uint32_t aH, uint32_t wBase,
                                          float* __restrict__ out,
                                          int T, int nh, int kg, int kb,
                                          int ns, int wm, int lane) {
    const uint32_t bRow = (lane & 7) + ((lane >> 4) & 1) * 8;
    const uint32_t bOff = ((lane >> 3) & 1) * 16;
    const uint32_t wHa = wBase + (kb * 64 + ns * 32 + bRow) * PITCH + bOff;

    float acc[2][4][4];
#pragma unroll
    for (int mt = 0; mt < 2; mt++)
#pragma unroll
        for (int nt = 0; nt < 4; nt++)
#pragma unroll
            for (int r = 0; r < 4; r++) acc[mt][nt][r] = 0.0f;

#pragma unroll
    for (int s = 0; s < STEPS; s++) {
        uint32_t ah[2][4];
        ldsm4(ah[0], aH + s * 32);
        ldsm4(ah[1], aH + 16 * PITCH + s * 32);
        uint32_t wh[2][4];
        ldsm4(wh[0], wHa + s * 32);
        ldsm4(wh[1], wHa + 16 * PITCH + s * 32);
#pragma unroll
        for (int mt = 0; mt < 2; mt++)
#pragma unroll
            for (int nt = 0; nt < 4; nt++)
                mma16816(acc[mt][nt], ah[mt], &wh[nt >> 1][(nt & 1) * 2]);
    }

    const int j  = T >> 3;
    const int b  = (T >> 1) & 3;
    const int h0 = (T & 1) << 7;
    const int k  = kg * 4 + nh * 2 + kb;
    const int t  = j * 64 + k;
    const size_t rowBase = (size_t)(b * 1024 + t) * 16384;
    const int rbase = lane >> 2;
    const int nb    = ns * 32 + (lane & 3) * 4;
#pragma unroll
    for (int mt = 0; mt < 2; mt++) {
        const int cl0 = wm * 32 + mt * 16 + rbase;
        float* p0 = out + rowBase + (size_t)(h0 + cl0) * 64 + nb;
        float* p1 = p0 + 8 * 64;
#pragma unroll
        for (int g = 0; g < 2; g++) {
            float4 v0 = make_float4(acc[mt][2 * g][0], acc[mt][2 * g][1],
                                    acc[mt][2 * g + 1][0], acc[mt][2 * g + 1][1]);
            float4 v1 = make_float4(acc[mt][2 * g][2], acc[mt][2 * g][3],
                                    acc[mt][2 * g + 1][2], acc[mt][2 * g + 1][3]);
            __stcs(reinterpret_cast<float4*>(p0 + g * 16), v0);
            __stcs(reinterpret_cast<float4*>(p1 + g * 16), v1);
        }
    }
}

// smallest q with C(q) >= s, where C(q) = 152*(q>>4) + P[q&15]
__device__ __forceinline__ int find_q(unsigned long long s) {
    const int P[16] = {0, 8, 16, 24, 32, 41, 50, 59, 68, 78, 88, 98,
                       108, 119, 130, 141};
    int blk = (int)(s / 152ull);
    int r = (int)(s - (unsigned long long)blk * 152ull);
    int j = 0;
#pragma unroll
    for (int k2 = 0; k2 < 16; k2++) j += (P[k2] < r) ? 1 : 0;
    return blk * 16 + j;
}

__global__ void __launch_bounds__(512, 2) gemm_kernel(float* __restrict__ out) {
    extern __shared__ char smg[];
    const uint32_t base = smem_u32(smg);
    const int tid = threadIdx.x;
    const int wid = tid >> 5, lane = tid & 31;
    const int kb = wid & 1, ns = (wid >> 1) & 1, wm = wid >> 2;

    const int lo = find_q((unsigned long long)blockIdx.x * WTOT / NGRID);
    const int hi = find_q((unsigned long long)(blockIdx.x + 1) * WTOT / NGRID);

    const uint32_t aRow = (lane & 7) + ((lane >> 3) & 1) * 8;
    const uint32_t aOff = ((lane >> 4) & 1) * 16;
    const uint32_t aH = base + (wm * 32 + aRow) * PITCH + aOff;

    int lastT = -1;
    int buf = 0;
    bool pending = false;
#pragma unroll 1
    for (int q = lo; q < hi; q++) {
        const int T = q >> 5, nh = (q >> 4) & 1, kg = q & 15;
        const int kq = kg >> 2;
        if (!pending) {
            if (T != lastT) {
                const __half* asrc = g_AugH + (size_t)T * 128 * 128;
                for (int i = tid; i < 2048; i += 512) {
                    int row = i >> 4, qq = i & 15;
                    cp16(base + row * PITCH + qq * 16,
                         asrc + (size_t)row * 128 + qq * 8);
                }
                lastT = T;
            }
            load_w(base, tid, kg, nh, buf, 5 + kq);
        }
        const bool pf = (q + 1 < hi) && ((q + 1) >> 5 == lastT);
        if (pf) {
            load_w(base, tid, (q + 1) & 15, ((q + 1) >> 4) & 1, buf ^ 1,
                   5 + (((q + 1) & 15) >> 2));
            cp_wait_n<1>();
        } else {
            cp_wait_n<0>();
        }
        __syncthreads();
        const uint32_t wBase = base + (128 + buf * 128) * PITCH;
        switch (kq) {
        case 0: gemm_iter<5>(aH, wBase, out, T, nh, kg, kb, ns, wm, lane); break;
        case 1: gemm_iter<6>(aH, wBase, out, T, nh, kg, kb, ns, wm, lane); break;
        case 2: gemm_iter<7>(aH, wBase, out, T, nh, kg, kb, ns, wm, lane); break;
        default: gemm_iter<8>(aH, wBase, out, T, nh, kg, kb, ns, wm, lane); break;
        }
        __syncthreads();
        buf ^= 1;
        pending = pf;
    }
}

// ---------------- launcher ----------------
extern "C" void kernel_launch(void* const* d_in, const int* in_sizes, int n_in,
                              void* d_out, int out_size) {
    const float* inp = (const float*)d_in[0];   // [4,1024,256]
    const float* A   = (const float*)d_in[1];   // [64,64]
    const float* Bv  = (const float*)d_in[2];   // [64]
    const float* x0  = (const float*)d_in[3];   // [4,256,64]
    float* out = (float*)d_out;

    cudaFuncSetAttribute(prep1_kernel,
                         cudaFuncAttributeMaxDynamicSharedMemorySize, PREP1_SMEM);
    prep1_kernel<<<129, 256, PREP1_SMEM>>>(A, Bv, inp);     // 1

    cudaFuncSetAttribute(prep2_kernel,
                         cudaFuncAttributeMaxDynamicSharedMemorySize, POW2_SMEM);
    prep2_kernel<<<192, 256, POW2_SMEM>>>(x0);              // 2

    cudaFuncSetAttribute(gemm_kernel,
                         cudaFuncAttributeMaxDynamicSharedMemorySize, GEMM_SMEM);
    gemm_kernel<<<NGRID, 512, GEMM_SMEM>>>(out);            // 3
}

// round 16
// speedup vs baseline: 1.3651x; 1.3651x over previous
#include <cuda_runtime.h>
#include <cuda_fp16.h>
#include <cuda_bf16.h>
#include <cstdint>
#include <cstddef>

// out = W[4096x128] @ Aug[128x16384] via mma.sync fp16.
// R12 prep (tensor-core square&multiply powers + fused vscanw) recombined
// with R13 GEMM (perm16 W rows -> float4 streaming epilogue).

#define NCHUNK 16
#define BHTOT  1024
#define NCOLS  (NCHUNK * BHTOT)   // 16384

// ---------------- scratch (static device memory) --------------------------
__device__ float g_P64[4096];               // A^64
__device__ float g_Kvec[64 * 64];           // K_d = A^d B
__device__ __align__(16) __half g_WH[64 * 8192];            // W fp16, per k 64x128
__device__ __align__(16) __half g_AugH[(size_t)NCOLS * 128];  // fp16(Aug)

// perm16: physical row within a 16-row W group for true n (epilogue float4)
__device__ __forceinline__ int perm16(int m) {
    return ((m >> 1) & 1) * 8 + (m >> 2) * 2 + (m & 1);
}

// ---------------- helpers ----------------
__device__ __forceinline__ uint32_t smem_u32(const void* p) {
    uint32_t a;
    asm("{ .reg .u64 t; cvta.to.shared.u64 t, %1; cvt.u32.u64 %0, t; }"
        : "=r"(a) : "l"(p));
    return a;
}
__device__ __forceinline__ void ldsm4(uint32_t* r, uint32_t addr) {
    asm volatile("ldmatrix.sync.aligned.m8n8.x4.shared.b16 {%0,%1,%2,%3}, [%4];"
                 : "=r"(r[0]), "=r"(r[1]), "=r"(r[2]), "=r"(r[3]) : "r"(addr));
}
__device__ __forceinline__ void mma16816(float* d, const uint32_t* a,
                                         const uint32_t* b) {
    asm volatile(
        "mma.sync.aligned.m16n8k16.row.col.f32.f16.f16.f32 "
        "{%0,%1,%2,%3},{%4,%5,%6,%7},{%8,%9},{%0,%1,%2,%3};"
        : "+f"(d[0]), "+f"(d[1]), "+f"(d[2]), "+f"(d[3])
        : "r"(a[0]), "r"(a[1]), "r"(a[2]), "r"(a[3]), "r"(b[0]), "r"(b[1]));
}
__device__ __forceinline__ void mma16816bf(float* d, const uint32_t* a,
                                           const uint32_t* b) {
    asm volatile(
        "mma.sync.aligned.m16n8k16.row.col.f32.bf16.bf16.f32 "
        "{%0,%1,%2,%3},{%4,%5,%6,%7},{%8,%9},{%0,%1,%2,%3};"
        : "+f"(d[0]), "+f"(d[1]), "+f"(d[2]), "+f"(d[3])
        : "r"(a[0]), "r"(a[1]), "r"(a[2]), "r"(a[3]), "r"(b[0]), "r"(b[1]));
}
__device__ __forceinline__ void cp16(uint32_t dst, const void* src) {
    asm volatile("cp.async.cg.shared.global [%0], [%1], 16;"
                 :: "r"(dst), "l"(src));
}
__device__ __forceinline__ void cp_commit() {
    asm volatile("cp.async.commit_group;" ::: "memory");
}
template <int N>
__device__ __forceinline__ void cp_wait_n() {
    asm volatile("cp.async.wait_group %0;" :: "n"(N) : "memory");
}

// ---------------- tensor-core 64x64 product (bf16x3) ----------------------
// Matrix group = 4 bf16 buffers (64x72): H_row, L_row, H_trans, L_trans.
#define TCP    72
#define BUFE   4608
#define GRPE   (4 * BUFE)
#define POW_SMEM (2 * GRPE * 2)     // 73728 B (two groups: pw, res)

__device__ __forceinline__ void pow_write(__nv_bfloat16* sm, int gD,
                                          int r, int c, float v) {
    __nv_bfloat16 hi = __float2bfloat16(v);
    __nv_bfloat16 lo = __float2bfloat16(v - __bfloat162float(hi));
    sm[gD + r * TCP + c]                = hi;
    sm[gD + BUFE + r * TCP + c]         = lo;
    sm[gD + 2 * BUFE + c * TCP + r]     = hi;
    sm[gD + 3 * BUFE + c * TCP + r]     = lo;
}

// D(group gD) = gA x gB; 256 threads; aliasing safe (reads before sync)
__device__ __forceinline__ void mm_tc(__nv_bfloat16* sm, uint32_t smb,
                                      int tid, int gA, int gB, int gD) {
    const int lane = tid & 31, wid = tid >> 5;
    const int m0 = (wid >> 1) * 16;
    const int n0 = (wid & 1) * 32;
    const uint32_t aRow = (lane & 7) + ((lane >> 3) & 1) * 8;
    const uint32_t aOff = ((lane >> 4) & 1) * 16;
    const uint32_t bRow = (lane & 7) + ((lane >> 4) & 1) * 8;
    const uint32_t bOff = ((lane >> 3) & 1) * 16;
    const uint32_t aB  = smb + (uint32_t)gA * 2 + (m0 + aRow) * 144 + aOff;
    const uint32_t b0B = smb + (uint32_t)(gB + 2 * BUFE) * 2
                             + (n0 + bRow) * 144 + bOff;
    const uint32_t b1B = b0B + 16 * 144;

    float acc[4][4];
#pragma unroll
    for (int nt = 0; nt < 4; nt++)
#pragma unroll
        for (int r = 0; r < 4; r++) acc[nt][r] = 0.0f;

#pragma unroll
    for (int k = 0; k < 4; k++) {
        uint32_t ah[4], al[4], b0h[4], b0l[4], b1h[4], b1l[4];
        ldsm4(ah,  aB + k * 32);
        ldsm4(al,  aB + BUFE * 2 + k * 32);
        ldsm4(b0h, b0B + k * 32);
        ldsm4(b0l, b0B + BUFE * 2 + k * 32);
        ldsm4(b1h, b1B + k * 32);
        ldsm4(b1l, b1B + BUFE * 2 + k * 32);
        mma16816bf(acc[0], ah, &b0h[0]); mma16816bf(acc[1], ah, &b0h[2]);
        mma16816bf(acc[2], ah, &b1h[0]); mma16816bf(acc[3], ah, &b1h[2]);
        mma16816bf(acc[0], ah, &b0l[0]); mma16816bf(acc[1], ah, &b0l[2]);
        mma16816bf(acc[2], ah, &b1l[0]); mma16816bf(acc[3], ah, &b1l[2]);
        mma16816bf(acc[0], al, &b0h[0]); mma16816bf(acc[1], al, &b0h[2]);
        mma16816bf(acc[2], al, &b1h[0]); mma16816bf(acc[3], al, &b1h[2]);
    }
    __syncthreads();
    const int r0 = m0 + (lane >> 2);
#pragma unroll
    for (int nt = 0; nt < 4; nt++) {
        const int c0 = n0 + nt * 8 + (lane & 3) * 2;
        pow_write(sm, gD, r0,     c0,     acc[nt][0]);
        pow_write(sm, gD, r0,     c0 + 1, acc[nt][1]);
        pow_write(sm, gD, r0 + 8, c0,     acc[nt][2]);
        pow_write(sm, gD, r0 + 8, c0 + 1, acc[nt][3]);
    }
    __syncthreads();
}

// ---------------- powers: CTA c = A^{c+1} (square&multiply), K, W P-half --
__global__ void __launch_bounds__(256, 1) powers_kernel(
    const float* __restrict__ A, const float* __restrict__ Bv) {
    extern __shared__ __nv_bfloat16 sm[];
    __shared__ float bs[64];
    const uint32_t smb = smem_u32(sm);
    const int c = blockIdx.x;     // 0..63
    const int e = c + 1;          // 1..64
    const int tid = threadIdx.x;

    // init pw group from A
    for (int i = tid; i < 4096; i += 256) {
        int r = i >> 6, cc = i & 63;
        pow_write(sm, 0, r, cc, A[i]);
    }
    if (tid < 64) bs[tid] = Bv[tid];
    __syncthreads();

    bool has = false;
    int rem = e;
    while (true) {
        if (rem & 1) {
            if (!has) {
                for (int i = tid; i < GRPE; i += 256) sm[GRPE + i] = sm[i];
                __syncthreads();
                has = true;
            } else {
                mm_tc(sm, smb, tid, GRPE, 0, GRPE);   // res = res x pw
            }
        }
        rem >>= 1;
        if (!rem) break;
        mm_tc(sm, smb, tid, 0, 0, 0);                 // pw = pw x pw
    }

    // W P-half (perm16 rows) + P64 + Kvec from res group (hi+lo)
    for (int i = tid; i < 4096; i += 256) {
        int n = i >> 6, m = i & 63;
        float v = __bfloat162float(sm[GRPE + n * TCP + m])
                + __bfloat162float(sm[GRPE + BUFE + n * TCP + m]);
        int np = (n & 48) | perm16(n & 15);
        g_WH[(size_t)c * 8192 + np * 128 + m] = __float2half(v);
        if (e == 64) g_P64[i] = v;
    }
    if (e <= 63 && tid < 64) {
        float a = 0.0f;
#pragma unroll 8
        for (int q = 0; q < 64; q++) {
            float v = __bfloat162float(sm[GRPE + tid * TCP + q])
                    + __bfloat162float(sm[GRPE + BUFE + tid * TCP + q]);
            a = fmaf(v, bs[q], a);
        }
        g_Kvec[e * 64 + tid] = a;
    }
    if (c == 0 && tid < 64) g_Kvec[tid] = bs[tid];
}

// ---------------- fused u-stage + v + scan + Aug both halves + W K-half ---
#define VS_SMEM (17024 * 4)

__global__ void __launch_bounds__(256) vscanw_kernel(
    const float* __restrict__ inp, const float* __restrict__ x0) {
    extern __shared__ float vs[];
    float* su   = vs;              // 8 x 1032
    float* sK   = vs + 8256;       // 4096
    float* sP   = vs + 12352;      // 64 x 65
    float* sbuf = vs + 16512;      // 8 x 64
    const int tid = threadIdx.x;
    const int bh0 = blockIdx.x * 8;
    const int b   = bh0 >> 8;
    const int h0  = bh0 & 255;

    // stage u block (32B-sector coalesced)
    {
        const float* src = inp + (size_t)b * 1024 * 256 + h0;
        const int hh = tid & 7;
        const int tb = tid >> 3;
#pragma unroll 4
        for (int it = 0; it < 32; it++) {
            int t = it * 32 + tb;
            su[hh * 1032 + t] = src[(size_t)t * 256 + hh];
        }
    }
    for (int i = tid; i < 4096; i += 256) {
        sK[i] = g_Kvec[i];
        sP[(i >> 6) * 65 + (i & 63)] = g_P64[i];
    }
    __syncthreads();

    // Aug u-half (fp16, coalesced)
    for (int idx = tid; idx < 8192; idx += 256) {
        int j = idx >> 9, hh = (idx >> 6) & 7, s = idx & 63;
        g_AugH[(size_t)(j * 1024 + bh0 + hh) * 128 + 64 + s] =
            __float2half(su[hh * 1032 + j * 64 + s]);
    }
    // W K-half triangle (perm16 rows): this CTA's 2048-element slice
    {
        int base_i = blockIdx.x * 2048;
        for (int ii = tid; ii < 2048; ii += 256) {
            int idx = base_i + ii;
            int k = idx >> 12, n = (idx >> 6) & 63, s = idx & 63;
            float val = (s <= k) ? sK[(k - s) * 64 + n] : 0.0f;
            int np = (n & 48) | perm16(n & 15);
            g_WH[(size_t)k * 8192 + np * 128 + 64 + s] = __float2half(val);
        }
    }

    const int w = tid >> 5, lane = tid & 31;
    const int bh = bh0 + w;
    float s0 = x0[(size_t)bh * 64 + lane];
    float s1 = x0[(size_t)bh * 64 + lane + 32];
    g_AugH[(size_t)bh * 128 + lane]      = __float2half(s0);
    g_AugH[(size_t)bh * 128 + lane + 32] = __float2half(s1);
#pragma unroll 1
    for (int j = 1; j < 16; j++) {
        sbuf[w * 64 + lane]      = s0;
        sbuf[w * 64 + lane + 32] = s1;
        __syncwarp();
        float a0 = 0.0f, a1 = 0.0f;
        const float* uj = su + w * 1032 + (j - 1) * 64;
#pragma unroll 8
        for (int s = 0; s < 64; s++) {
            float u = uj[s];
            a0 = fmaf(sK[(63 - s) * 64 + lane], u, a0);
            a1 = fmaf(sK[(63 - s) * 64 + lane + 32], u, a1);
        }
#pragma unroll 8
        for (int q = 0; q < 64; q++) {
            float xq = sbuf[w * 64 + q];
            a0 = fmaf(sP[lane * 65 + q], xq, a0);
            a1 = fmaf(sP[(lane + 32) * 65 + q], xq, a1);
        }
        __syncwarp();
        s0 = a0; s1 = a1;
        g_AugH[(size_t)(j * 1024 + bh) * 128 + lane]      = __float2half(s0);
        g_AugH[(size_t)(j * 1024 + bh) * 128 + lane + 32] = __float2half(s1);
    }
}

// ---------------- persistent mma.sync GEMM, weighted static schedule ------
#define PITCH    272
#define GEMM_SMEM (384 * 272)    // 104448
#define NGRID    296
#define WTOT     38912ull        // 256 groups x 152

__device__ __forceinline__ void load_w(uint32_t base, int tid, int kg, int nh,
                                       int buf, int steps) {
    const int qmax = 2 * steps;
    const __half* wsrc = g_WH + (size_t)(kg * 4 + nh * 2) * 64 * 128;
    uint32_t dst0 = base + (128 + buf * 128) * PITCH;
    for (int i = tid; i < 2048; i += 512) {
        int row = i >> 4, q = i & 15;
        if (q < qmax)
            cp16(dst0 + row * PITCH + q * 16, wsrc + (size_t)row * 128 + q * 8);
    }
    cp_commit();
}

template <int STEPS>
__device__ __forceinline__ void gemm_iter(uint32_t aH, uint32_t wBase,
                                          float* __restrict__ out,
                                          int T, int nh, int kg, int kb,
                                          int ns, int wm, int lane) {
    const uint32_t bRow = (lane & 7) + ((lane >> 4) & 1) * 8;
    const uint32_t bOff = ((lane >> 3) & 1) * 16;
    const uint32_t wHa = wBase + (kb * 64 + ns * 32 + bRow) * PITCH + bOff;

    float acc[2][4][4];
#pragma unroll
    for (int mt = 0; mt < 2; mt++)
#pragma unroll
        for (int nt = 0; nt < 4; nt++)
#pragma unroll
            for (int r = 0; r < 4; r++) acc[mt][nt][r] = 0.0f;

#pragma unroll
    for (int s = 0; s < STEPS; s++) {
        uint32_t ah[2][4];
        ldsm4(ah[0], aH + s * 32);
        ldsm4(ah[1], aH + 16 * PITCH + s * 32);
        uint32_t wh[2][4];
        ldsm4(wh[0], wHa + s * 32);
        ldsm4(wh[1], wHa + 16 * PITCH + s * 32);
#pragma unroll
        for (int mt = 0; mt < 2; mt++)
#pragma unroll
            for (int nt = 0; nt < 4; nt++)
                mma16816(acc[mt][nt], ah[mt], &wh[nt >> 1][(nt & 1) * 2]);
    }

    const int j  = T >> 3;
    const int b  = (T >> 1) & 3;
    const int h0 = (T & 1) << 7;
    const int k  = kg * 4 + nh * 2 + kb;
    const int t  = j * 64 + k;
    const size_t rowBase = (size_t)(b * 1024 + t) * 16384;
    const int rbase = lane >> 2;
    const int nb    = ns * 32 + (lane & 3) * 4;
#pragma unroll
    for (int mt = 0; mt < 2; mt++) {
        const int cl0 = wm * 32 + mt * 16 + rbase;
        float* p0 = out + rowBase + (size_t)(h0 + cl0) * 64 + nb;
        float* p1 = p0 + 8 * 64;
#pragma unroll
        for (int g = 0; g < 2; g++) {
            float4 v0 = make_float4(acc[mt][2 * g][0], acc[mt][2 * g][1],
                                    acc[mt][2 * g + 1][0], acc[mt][2 * g + 1][1]);
            float4 v1 = make_float4(acc[mt][2 * g][2], acc[mt][2 * g][3],
                                    acc[mt][2 * g + 1][2], acc[mt][2 * g + 1][3]);
            __stcs(reinterpret_cast<float4*>(p0 + g * 16), v0);
            __stcs(reinterpret_cast<float4*>(p1 + g * 16), v1);
        }
    }
}

// smallest q with C(q) >= s, where C(q) = 152*(q>>4) + P[q&15]
__device__ __forceinline__ int find_q(unsigned long long s) {
    const int P[16] = {0, 8, 16, 24, 32, 41, 50, 59, 68, 78, 88, 98,
                       108, 119, 130, 141};
    int blk = (int)(s / 152ull);
    int r = (int)(s - (unsigned long long)blk * 152ull);
    int j = 0;
#pragma unroll
    for (int k2 = 0; k2 < 16; k2++) j += (P[k2] < r) ? 1 : 0;
    return blk * 16 + j;
}

__global__ void __launch_bounds__(512, 2) gemm_kernel(float* __restrict__ out) {
    extern __shared__ char smg[];
    const uint32_t base = smem_u32(smg);
    const int tid = threadIdx.x;
    const int wid = tid >> 5, lane = tid & 31;
    const int kb = wid & 1, ns = (wid >> 1) & 1, wm = wid >> 2;

    const int lo = find_q((unsigned long long)blockIdx.x * WTOT / NGRID);
    const int hi = find_q((unsigned long long)(blockIdx.x + 1) * WTOT / NGRID);

    const uint32_t aRow = (lane & 7) + ((lane >> 3) & 1) * 8;
    const uint32_t aOff = ((lane >> 4) & 1) * 16;
    const uint32_t aH = base + (wm * 32 + aRow) * PITCH + aOff;

    int lastT = -1;
    int buf = 0;
    bool pending = false;
#pragma unroll 1
    for (int q = lo; q < hi; q++) {
        const int T = q >> 5, nh = (q >> 4) & 1, kg = q & 15;
        const int kq = kg >> 2;
        if (!pending) {
            if (T != lastT) {
                const __half* asrc = g_AugH + (size_t)T * 128 * 128;
                for (int i = tid; i < 2048; i += 512) {
                    int row = i >> 4, qq = i & 15;
                    cp16(base + row * PITCH + qq * 16,
                         asrc + (size_t)row * 128 + qq * 8);
                }
                lastT = T;
            }
            load_w(base, tid, kg, nh, buf, 5 + kq);
        }
        const bool pf = (q + 1 < hi) && ((q + 1) >> 5 == lastT);
        if (pf) {
            load_w(base, tid, (q + 1) & 15, ((q + 1) >> 4) & 1, buf ^ 1,
                   5 + (((q + 1) & 15) >> 2));
            cp_wait_n<1>();
        } else {
            cp_wait_n<0>();
        }
        __syncthreads();
        const uint32_t wBase = base + (128 + buf * 128) * PITCH;
        switch (kq) {
        case 0: gemm_iter<5>(aH, wBase, out, T, nh, kg, kb, ns, wm, lane); break;
        case 1: gemm_iter<6>(aH, wBase, out, T, nh, kg, kb, ns, wm, lane); break;
        case 2: gemm_iter<7>(aH, wBase, out, T, nh, kg, kb, ns, wm, lane); break;
        default: gemm_iter<8>(aH, wBase, out, T, nh, kg, kb, ns, wm, lane); break;
        }
        __syncthreads();
        buf ^= 1;
        pending = pf;
    }
}

// ---------------- launcher ----------------
extern "C" void kernel_launch(void* const* d_in, const int* in_sizes, int n_in,
                              void* d_out, int out_size) {
    const float* inp = (const float*)d_in[0];   // [4,1024,256]
    const float* A   = (const float*)d_in[1];   // [64,64]
    const float* Bv  = (const float*)d_in[2];   // [64]
    const float* x0  = (const float*)d_in[3];   // [4,256,64]
    float* out = (float*)d_out;

    cudaFuncSetAttribute(powers_kernel,
                         cudaFuncAttributeMaxDynamicSharedMemorySize, POW_SMEM);
    powers_kernel<<<64, 256, POW_SMEM>>>(A, Bv);            // 1

    cudaFuncSetAttribute(vscanw_kernel,
                         cudaFuncAttributeMaxDynamicSharedMemorySize, VS_SMEM);
    vscanw_kernel<<<128, 256, VS_SMEM>>>(inp, x0);          // 2

    cudaFuncSetAttribute(gemm_kernel,
                         cudaFuncAttributeMaxDynamicSharedMemorySize, GEMM_SMEM);
    gemm_kernel<<<NGRID, 512, GEMM_SMEM>>>(out);            // 3
}

// round 17
// speedup vs baseline: 1.4442x; 1.0580x over previous
#include <cuda_runtime.h>
#include <cuda_fp16.h>
#include <cuda_bf16.h>
#include <cstdint>
#include <cstddef>

// out = W[4096x128] @ Aug[128x16384] via mma.sync fp16.
// powers: tensor-core square&multiply, 512 thr (short chain latency).
// GEMM: 256-thr CTAs occ 2, warp tile 32Mx64N (fewer ldsm per MMA).

#define NCHUNK 16
#define BHTOT  1024
#define NCOLS  (NCHUNK * BHTOT)   // 16384

// ---------------- scratch (static device memory) --------------------------
__device__ float g_P64[4096];               // A^64
__device__ float g_Kvec[64 * 64];           // K_d = A^d B
__device__ __align__(16) __half g_WH[64 * 8192];            // W fp16, per k 64x128
__device__ __align__(16) __half g_AugH[(size_t)NCOLS * 128];  // fp16(Aug)

// perm16: physical row within a 16-row W group for true n (epilogue float4)
__device__ __forceinline__ int perm16(int m) {
    return ((m >> 1) & 1) * 8 + (m >> 2) * 2 + (m & 1);
}

// ---------------- helpers ----------------
__device__ __forceinline__ uint32_t smem_u32(const void* p) {
    uint32_t a;
    asm("{ .reg .u64 t; cvta.to.shared.u64 t, %1; cvt.u32.u64 %0, t; }"
        : "=r"(a) : "l"(p));
    return a;
}
__device__ __forceinline__ void ldsm4(uint32_t* r, uint32_t addr) {
    asm volatile("ldmatrix.sync.aligned.m8n8.x4.shared.b16 {%0,%1,%2,%3}, [%4];"
                 : "=r"(r[0]), "=r"(r[1]), "=r"(r[2]), "=r"(r[3]) : "r"(addr));
}
__device__ __forceinline__ void mma16816(float* d, const uint32_t* a,
                                         const uint32_t* b) {
    asm volatile(
        "mma.sync.aligned.m16n8k16.row.col.f32.f16.f16.f32 "
        "{%0,%1,%2,%3},{%4,%5,%6,%7},{%8,%9},{%0,%1,%2,%3};"
        : "+f"(d[0]), "+f"(d[1]), "+f"(d[2]), "+f"(d[3])
        : "r"(a[0]), "r"(a[1]), "r"(a[2]), "r"(a[3]), "r"(b[0]), "r"(b[1]));
}
__device__ __forceinline__ void mma16816bf(float* d, const uint32_t* a,
                                           const uint32_t* b) {
    asm volatile(
        "mma.sync.aligned.m16n8k16.row.col.f32.bf16.bf16.f32 "
        "{%0,%1,%2,%3},{%4,%5,%6,%7},{%8,%9},{%0,%1,%2,%3};"
        : "+f"(d[0]), "+f"(d[1]), "+f"(d[2]), "+f"(d[3])
        : "r"(a[0]), "r"(a[1]), "r"(a[2]), "r"(a[3]), "r"(b[0]), "r"(b[1]));
}
__device__ __forceinline__ void cp16(uint32_t dst, const void* src) {
    asm volatile("cp.async.cg.shared.global [%0], [%1], 16;"
                 :: "r"(dst), "l"(src));
}
__device__ __forceinline__ void cp_commit() {
    asm volatile("cp.async.commit_group;" ::: "memory");
}
template <int N>
__device__ __forceinline__ void cp_wait_n() {
    asm volatile("cp.async.wait_group %0;" :: "n"(N) : "memory");
}

// ---------------- tensor-core 64x64 product (bf16x3), 512 threads ---------
// Matrix group = 4 bf16 buffers (64x72): H_row, L_row, H_trans, L_trans.
#define TCP    72
#define BUFE   4608
#define GRPE   (4 * BUFE)
#define POW_SMEM (2 * GRPE * 2)     // 73728 B (two groups: pw, res)

__device__ __forceinline__ void pow_write(__nv_bfloat16* sm, int gD,
                                          int r, int c, float v) {
    __nv_bfloat16 hi = __float2bfloat16(v);
    __nv_bfloat16 lo = __float2bfloat16(v - __bfloat162float(hi));
    sm[gD + r * TCP + c]                = hi;
    sm[gD + BUFE + r * TCP + c]         = lo;
    sm[gD + 2 * BUFE + c * TCP + r]     = hi;
    sm[gD + 3 * BUFE + c * TCP + r]     = lo;
}

// D(group gD) = gA x gB; 512 threads (16 warps, 16x16 tiles)
__device__ __forceinline__ void mm_tc(__nv_bfloat16* sm, uint32_t smb,
                                      int tid, int gA, int gB, int gD) {
    const int lane = tid & 31, wid = tid >> 5;
    const int m0 = (wid >> 2) * 16;
    const int n0 = (wid & 3) * 16;
    const uint32_t aRow = (lane & 7) + ((lane >> 3) & 1) * 8;
    const uint32_t aOff = ((lane >> 4) & 1) * 16;
    const uint32_t bRow = (lane & 7) + ((lane >> 4) & 1) * 8;
    const uint32_t bOff = ((lane >> 3) & 1) * 16;
    const uint32_t aB = smb + (uint32_t)gA * 2 + (m0 + aRow) * 144 + aOff;
    const uint32_t bB = smb + (uint32_t)(gB + 2 * BUFE) * 2
                            + (n0 + bRow) * 144 + bOff;

    float acc[2][4];
#pragma unroll
    for (int nt = 0; nt < 2; nt++)
#pragma unroll
        for (int r = 0; r < 4; r++) acc[nt][r] = 0.0f;

#pragma unroll
    for (int k = 0; k < 4; k++) {
        uint32_t ah[4], al[4], bh[4], bl[4];
        ldsm4(ah, aB + k * 32);
        ldsm4(al, aB + BUFE * 2 + k * 32);
        ldsm4(bh, bB + k * 32);
        ldsm4(bl, bB + BUFE * 2 + k * 32);
        mma16816bf(acc[0], ah, &bh[0]); mma16816bf(acc[1], ah, &bh[2]);
        mma16816bf(acc[0], ah, &bl[0]); mma16816bf(acc[1], ah, &bl[2]);
        mma16816bf(acc[0], al, &bh[0]); mma16816bf(acc[1], al, &bh[2]);
    }
    __syncthreads();
    const int r0 = m0 + (lane >> 2);
#pragma unroll
    for (int nt = 0; nt < 2; nt++) {
        const int c0 = n0 + nt * 8 + (lane & 3) * 2;
        pow_write(sm, gD, r0,     c0,     acc[nt][0]);
        pow_write(sm, gD, r0,     c0 + 1, acc[nt][1]);
        pow_write(sm, gD, r0 + 8, c0,     acc[nt][2]);
        pow_write(sm, gD, r0 + 8, c0 + 1, acc[nt][3]);
    }
    __syncthreads();
}

// ---------------- powers: CTA c = A^{c+1} (square&multiply), K, W P-half --
__global__ void __launch_bounds__(512, 1) powers_kernel(
    const float* __restrict__ A, const float* __restrict__ Bv) {
    extern __shared__ __nv_bfloat16 sm[];
    __shared__ float bs[64];
    const uint32_t smb = smem_u32(sm);
    const int c = blockIdx.x;     // 0..63
    const int e = c + 1;          // 1..64
    const int tid = threadIdx.x;

    for (int i = tid; i < 4096; i += 512) {
        int r = i >> 6, cc = i & 63;
        pow_write(sm, 0, r, cc, A[i]);
    }
    if (tid < 64) bs[tid] = Bv[tid];
    __syncthreads();

    bool has = false;
    int rem = e;
    while (true) {
        if (rem & 1) {
            if (!has) {
                for (int i = tid; i < GRPE; i += 512) sm[GRPE + i] = sm[i];
                __syncthreads();
                has = true;
            } else {
                mm_tc(sm, smb, tid, GRPE, 0, GRPE);   // res = res x pw
            }
        }
        rem >>= 1;
        if (!rem) break;
        mm_tc(sm, smb, tid, 0, 0, 0);                 // pw = pw x pw
    }

    // W P-half (perm16 rows) + P64 + Kvec from res group (hi+lo)
    for (int i = tid; i < 4096; i += 512) {
        int n = i >> 6, m = i & 63;
        float v = __bfloat162float(sm[GRPE + n * TCP + m])
                + __bfloat162float(sm[GRPE + BUFE + n * TCP + m]);
        int np = (n & 48) | perm16(n & 15);
        g_WH[(size_t)c * 8192 + np * 128 + m] = __float2half(v);
        if (e == 64) g_P64[i] = v;
    }
    if (e <= 63 && tid < 64) {
        float a = 0.0f;
#pragma unroll 8
        for (int q = 0; q < 64; q++) {
            float v = __bfloat162float(sm[GRPE + tid * TCP + q])
                    + __bfloat162float(sm[GRPE + BUFE + tid * TCP + q]);
            a = fmaf(v, bs[q], a);
        }
        g_Kvec[e * 64 + tid] = a;
    }
    if (c == 0 && tid < 64) g_Kvec[tid] = bs[tid];
}

// ---------------- fused u-stage + v + scan + Aug both halves + W K-half ---
#define VS_SMEM (17024 * 4)

__global__ void __launch_bounds__(256) vscanw_kernel(
    const float* __restrict__ inp, const float* __restrict__ x0) {
    extern __shared__ float vs[];
    float* su   = vs;              // 8 x 1032
    float* sK   = vs + 8256;       // 4096
    float* sP   = vs + 12352;      // 64 x 65
    float* sbuf = vs + 16512;      // 8 x 64
    const int tid = threadIdx.x;
    const int bh0 = blockIdx.x * 8;
    const int b   = bh0 >> 8;
    const int h0  = bh0 & 255;

    {
        const float* src = inp + (size_t)b * 1024 * 256 + h0;
        const int hh = tid & 7;
        const int tb = tid >> 3;
#pragma unroll 4
        for (int it = 0; it < 32; it++) {
            int t = it * 32 + tb;
            su[hh * 1032 + t] = src[(size_t)t * 256 + hh];
        }
    }
    for (int i = tid; i < 4096; i += 256) {
        sK[i] = g_Kvec[i];
        sP[(i >> 6) * 65 + (i & 63)] = g_P64[i];
    }
    __syncthreads();

    for (int idx = tid; idx < 8192; idx += 256) {
        int j = idx >> 9, hh = (idx >> 6) & 7, s = idx & 63;
        g_AugH[(size_t)(j * 1024 + bh0 + hh) * 128 + 64 + s] =
            __float2half(su[hh * 1032 + j * 64 + s]);
    }
    {
        int base_i = blockIdx.x * 2048;
        for (int ii = tid; ii < 2048; ii += 256) {
            int idx = base_i + ii;
            int k = idx >> 12, n = (idx >> 6) & 63, s = idx & 63;
            float val = (s <= k) ? sK[(k - s) * 64 + n] : 0.0f;
            int np = (n & 48) | perm16(n & 15);
            g_WH[(size_t)k * 8192 + np * 128 + 64 + s] = __float2half(val);
        }
    }

    const int w = tid >> 5, lane = tid & 31;
    const int bh = bh0 + w;
    float s0 = x0[(size_t)bh * 64 + lane];
    float s1 = x0[(size_t)bh * 64 + lane + 32];
    g_AugH[(size_t)bh * 128 + lane]      = __float2half(s0);
    g_AugH[(size_t)bh * 128 + lane + 32] = __float2half(s1);
#pragma unroll 1
    for (int j = 1; j < 16; j++) {
        sbuf[w * 64 + lane]      = s0;
        sbuf[w * 64 + lane + 32] = s1;
        __syncwarp();
        float a0 = 0.0f, a1 = 0.0f;
        const float* uj = su + w * 1032 + (j - 1) * 64;
#pragma unroll 8
        for (int s = 0; s < 64; s++) {
            float u = uj[s];
            a0 = fmaf(sK[(63 - s) * 64 + lane], u, a0);
            a1 = fmaf(sK[(63 - s) * 64 + lane + 32], u, a1);
        }
#pragma unroll 8
        for (int q = 0; q < 64; q++) {
            float xq = sbuf[w * 64 + q];
            a0 = fmaf(sP[lane * 65 + q], xq, a0);
            a1 = fmaf(sP[(lane + 32) * 65 + q], xq, a1);
        }
        __syncwarp();
        s0 = a0; s1 = a1;
        g_AugH[(size_t)(j * 1024 + bh) * 128 + lane]      = __float2half(s0);
        g_AugH[(size_t)(j * 1024 + bh) * 128 + lane + 32] = __float2half(s1);
    }
}

// ---------------- persistent mma.sync GEMM, weighted static schedule ------
// 256-thr CTAs (8 warps), occ 2: wm = wid>>1 (32 M rows), kb = wid&1.
// Warp tile 32M x 64N (full k-block). Tickets q: T=q>>5, nh=(q>>4)&1, kg=q&15.
#define PITCH    272
#define GEMM_SMEM (384 * 272)    // 104448
#define NGRID    296
#define WTOT     38912ull        // 256 groups x 152

__device__ __forceinline__ void load_w(uint32_t base, int tid, int kg, int nh,
                                       int buf, int steps) {
    const int qmax = 2 * steps;
    const __half* wsrc = g_WH + (size_t)(kg * 4 + nh * 2) * 64 * 128;
    uint32_t dst0 = base + (128 + buf * 128) * PITCH;
    for (int i = tid; i < 2048; i += 256) {
        int row = i >> 4, q = i & 15;
        if (q < qmax)
            cp16(dst0 + row * PITCH + q * 16, wsrc + (size_t)row * 128 + q * 8);
    }
    cp_commit();
}

template <int STEPS>
__device__ __forceinline__ void gemm_iter(uint32_t aH, uint32_t wBase,
                                          float* __restrict__ out,
                                          int T, int nh, int kg, int kb,
                                          int wm, int lane) {
    const uint32_t bRow = (lane & 7) + ((lane >> 4) & 1) * 8;
    const uint32_t bOff = ((lane >> 3) & 1) * 16;
    const uint32_t wHa = wBase + (kb * 64 + bRow) * PITCH + bOff;

    float acc[2][8][4];
#pragma unroll
    for (int mt = 0; mt < 2; mt++)
#pragma unroll
        for (int nt = 0; nt < 8; nt++)
#pragma unroll
            for (int r = 0; r < 4; r++) acc[mt][nt][r] = 0.0f;

#pragma unroll
    for (int s = 0; s < STEPS; s++) {
        uint32_t ah[2][4];
        ldsm4(ah[0], aH + s * 32);
        ldsm4(ah[1], aH + 16 * PITCH + s * 32);
        uint32_t wh[4][4];
#pragma unroll
        for (int g = 0; g < 4; g++)
            ldsm4(wh[g], wHa + g * (16 * PITCH) + s * 32);
#pragma unroll
        for (int mt = 0; mt < 2; mt++)
#pragma unroll
            for (int g = 0; g < 4; g++) {
                mma16816(acc[mt][2 * g],     ah[mt], &wh[g][0]);
                mma16816(acc[mt][2 * g + 1], ah[mt], &wh[g][2]);
            }
    }

    const int j  = T >> 3;
    const int b  = (T >> 1) & 3;
    const int h0 = (T & 1) << 7;
    const int k  = kg * 4 + nh * 2 + kb;
    const int t  = j * 64 + k;
    const size_t rowBase = (size_t)(b * 1024 + t) * 16384;
    const int rbase = lane >> 2;
    const int nb    = (lane & 3) * 4;
#pragma unroll
    for (int mt = 0; mt < 2; mt++) {
        const int cl0 = wm * 32 + mt * 16 + rbase;
        float* p0 = out + rowBase + (size_t)(h0 + cl0) * 64 + nb;
        float* p1 = p0 + 8 * 64;
#pragma unroll
        for (int g = 0; g < 4; g++) {
            float4 v0 = make_float4(acc[mt][2 * g][0], acc[mt][2 * g][1],
                                    acc[mt][2 * g + 1][0], acc[mt][2 * g + 1][1]);
            float4 v1 = make_float4(acc[mt][2 * g][2], acc[mt][2 * g][3],
                                    acc[mt][2 * g + 1][2], acc[mt][2 * g + 1][3]);
            __stcs(reinterpret_cast<float4*>(p0 + g * 16), v0);
            __stcs(reinterpret_cast<float4*>(p1 + g * 16), v1);
        }
    }
}

// smallest q with C(q) >= s, where C(q) = 152*(q>>4) + P[q&15]
__device__ __forceinline__ int find_q(unsigned long long s) {
    const int P[16] = {0, 8, 16, 24, 32, 41, 50, 59, 68, 78, 88, 98,
                       108, 119, 130, 141};
    int blk = (int)(s / 152ull);
    int r = (int)(s - (unsigned long long)blk * 152ull);
    int j = 0;
#pragma unroll
    for (int k2 = 0; k2 < 16; k2++) j += (P[k2] < r) ? 1 : 0;
    return blk * 16 + j;
}

__global__ void __launch_bounds__(256, 2) gemm_kernel(float* __restrict__ out) {
    extern __shared__ char smg[];
    const uint32_t base = smem_u32(smg);
    const int tid = threadIdx.x;
    const int wid = tid >> 5, lane = tid & 31;
    const int kb = wid & 1, wm = wid >> 1;

    const int lo = find_q((unsigned long long)blockIdx.x * WTOT / NGRID);
    const int hi = find_q((unsigned long long)(blockIdx.x + 1) * WTOT / NGRID);

    const uint32_t aRow = (lane & 7) + ((lane >> 3) & 1) * 8;
    const uint32_t aOff = ((lane >> 4) & 1) * 16;
    const uint32_t aH = base + (wm * 32 + aRow) * PITCH + aOff;

    int lastT = -1;
    int buf = 0;
    bool pending = false;
#pragma unroll 1
    for (int q = lo; q < hi; q++) {
        const int T = q >> 5, nh = (q >> 4) & 1, kg = q & 15;
        const int kq = kg >> 2;
        if (!pending) {
            if (T != lastT) {
                const __half* asrc = g_AugH + (size_t)T * 128 * 128;
                for (int i = tid; i < 2048; i += 256) {
                    int row = i >> 4, qq = i & 15;
                    cp16(base + row * PITCH + qq * 16,
                         asrc + (size_t)row * 128 + qq * 8);
                }
                lastT = T;
            }
            load_w(base, tid, kg, nh, buf, 5 + kq);
        }
        const bool pf = (q + 1 < hi) && ((q + 1) >> 5 == lastT);
        if (pf) {
            load_w(base, tid, (q + 1) & 15, ((q + 1) >> 4) & 1, buf ^ 1,
                   5 + (((q + 1) & 15) >> 2));
            cp_wait_n<1>();
        } else {
            cp_wait_n<0>();
        }
        __syncthreads();
        const uint32_t wBase = base + (128 + buf * 128) * PITCH;
        switch (kq) {
        case 0: gemm_iter<5>(aH, wBase, out, T, nh, kg, kb, wm, lane); break;
        case 1: gemm_iter<6>(aH, wBase, out, T, nh, kg, kb, wm, lane); break;
        case 2: gemm_iter<7>(aH, wBase, out, T, nh, kg, kb, wm, lane); break;
        default: gemm_iter<8>(aH, wBase, out, T, nh, kg, kb, wm, lane); break;
        }
        __syncthreads();
        buf ^= 1;
        pending = pf;
    }
}

// ---------------- launcher ----------------
extern "C" void kernel_launch(void* const* d_in, const int* in_sizes, int n_in,
                              void* d_out, int out_size) {
    const float* inp = (const float*)d_in[0];   // [4,1024,256]
    const float* A   = (const float*)d_in[1];   // [64,64]
    const float* Bv  = (const float*)d_in[2];   // [64]
    const float* x0  = (const float*)d_in[3];   // [4,256,64]
    float* out = (float*)d_out;

    cudaFuncSetAttribute(powers_kernel,
                         cudaFuncAttributeMaxDynamicSharedMemorySize, POW_SMEM);
    powers_kernel<<<64, 512, POW_SMEM>>>(A, Bv);            // 1

    cudaFuncSetAttribute(vscanw_kernel,
                         cudaFuncAttributeMaxDynamicSharedMemorySize, VS_SMEM);
    vscanw_kernel<<<128, 256, VS_SMEM>>>(inp, x0);          // 2

    cudaFuncSetAttribute(gemm_kernel,
                         cudaFuncAttributeMaxDynamicSharedMemorySize, GEMM_SMEM);
    gemm_kernel<<<NGRID, 256, GEMM_SMEM>>>(out);            // 3
}